// round 17
// baseline (speedup 1.0000x reference)
#include <cuda_runtime.h>
#include <cuda_fp16.h>
#include <cstdint>

// Problem constants
constexpr int BB = 256;     // batch
constexpr int H  = 1024;    // hidden
constexpr int L  = 10000;   // labels
constexpr int MT = 128;     // M per CTA
constexpr int LPB = 16;     // labels per CTA (N = 128)
constexpr int KC = 64;      // K per chunk
constexpr int NCHUNK = H / KC;  // 16
constexpr int NSTAGE_A = 3;

// smem: A 3 stages x 16KB | B16 2 bufs x 16KB | B32 raw fp32 1 buf x 32KB
constexpr int OFF_A   = 0;
constexpr int A_STAGE = 16384;
constexpr int OFF_B16 = NSTAGE_A * A_STAGE;      // 49152
constexpr int B16_BUF = 16384;
constexpr int OFF_B32 = OFF_B16 + 2 * B16_BUF;   // 81920
constexpr int SMEM_DYN = 128 + OFF_B32 + 32768;  // 114816

// pre-converted fp16 embeddings [256][1024]
__device__ __align__(16) __half g_eA[BB * H];

// ---------------- helpers ----------------
__device__ __forceinline__ uint32_t smem_u32(const void* p) {
    uint32_t a;
    asm("{ .reg .u64 t; cvta.to.shared.u64 t, %1; cvt.u32.u64 %0, t; }" : "=r"(a) : "l"(p));
    return a;
}
__device__ __forceinline__ void cpasync16(uint32_t dst, const void* src) {
    asm volatile("cp.async.cg.shared.global [%0], [%1], 16;" :: "r"(dst), "l"(src));
}
#define CP_COMMIT() asm volatile("cp.async.commit_group;" ::: "memory")
#define CP_WAIT1()  asm volatile("cp.async.wait_group 1;" ::: "memory")
#define CP_WAIT0()  asm volatile("cp.async.wait_group 0;" ::: "memory")

__device__ __forceinline__ void ldsm4(uint32_t* r, uint32_t addr) {
    asm volatile("ldmatrix.sync.aligned.m8n8.x4.shared.b16 {%0,%1,%2,%3}, [%4];"
                 : "=r"(r[0]), "=r"(r[1]), "=r"(r[2]), "=r"(r[3]) : "r"(addr));
}
__device__ __forceinline__ void ldsm4t(uint32_t* r, uint32_t addr) {
    asm volatile("ldmatrix.sync.aligned.m8n8.x4.trans.shared.b16 {%0,%1,%2,%3}, [%4];"
                 : "=r"(r[0]), "=r"(r[1]), "=r"(r[2]), "=r"(r[3]) : "r"(addr));
}
__device__ __forceinline__ void mma16816(float* c, const uint32_t* a, const uint32_t* b) {
    asm volatile(
        "mma.sync.aligned.m16n8k16.row.col.f32.f16.f16.f32 "
        "{%0,%1,%2,%3}, {%4,%5,%6,%7}, {%8,%9}, {%0,%1,%2,%3};"
        : "+f"(c[0]), "+f"(c[1]), "+f"(c[2]), "+f"(c[3])
        : "r"(a[0]), "r"(a[1]), "r"(a[2]), "r"(a[3]), "r"(b[0]), "r"(b[1]));
}
__device__ __forceinline__ uint32_t pkh2(float x0, float x1) {
    __half2 h = __float22half2_rn(make_float2(x0, x1));
    return *reinterpret_cast<uint32_t*>(&h);
}

// ---------------- pre-kernel: emb fp32 -> fp16 ----------------
__global__ void cvt_emb_kernel(const float* __restrict__ emb) {
    int i = blockIdx.x * blockDim.x + threadIdx.x;   // 65536 float4s
    float4 v = reinterpret_cast<const float4*>(emb)[i];
    reinterpret_cast<uint2*>(g_eA)[i] = make_uint2(pkh2(v.x, v.y), pkh2(v.z, v.w));
}

// ---------------- main kernel ----------------
__global__ __launch_bounds__(256, 2)
void imec_hmma_kernel(const float* __restrict__ W1,
                      const float* __restrict__ b1,
                      const float* __restrict__ W2,
                      const float* __restrict__ b2,
                      float* __restrict__ out)
{
    extern __shared__ char smraw[];
    uint32_t sraw = smem_u32(smraw);
    uint32_t sb = (sraw + 127u) & ~127u;
    char* smc = smraw + (sb - sraw);

    const int tid  = threadIdx.x;
    const int lane = tid & 31;
    const int wid  = tid >> 5;        // 0..7
    const int wm   = wid & 1;         // warp M group: 64 rows each (2x64=128)
    const int wn   = wid >> 1;        // warp N group: 32 cols = 4 labels (4x32=128)

    const int lg = blockIdx.x >> 1;
    const int mt = blockIdx.x & 1;
    const int m0 = mt * MT;
    const int l0 = lg * LPB;

    // ---- A staging: thread -> (row, k-half), 128B swizzled rows ----
    const int ar = tid >> 1;          // 0..127
    const int ahalf = tid & 1;
    const char* aSrc = reinterpret_cast<const char*>(g_eA)
                     + (size_t)(m0 + ar) * (H * 2) + ahalf * 64;
    const uint32_t aDstBase = (uint32_t)(ar * 128);
    const uint32_t arx = (uint32_t)(ar & 7);

    // ---- B raw staging (cp.async fp32): thread -> (label, 8x16B units) ----
    const int blt = tid >> 4;         // label 0..15
    const int bu0 = tid & 15;         // unit 0..15
    const char* b32Src = reinterpret_cast<const char*>(W1)
                       + (size_t)(l0 + blt) * (H * 8 * 4);  // label base (bytes)
    const uint32_t b32Dst = (uint32_t)(blt * 2048 + bu0 * 16);

    // ---- B conversion: warp owns 2 labels (2*wid, 2*wid+1) ----
    const uint32_t cvtSrc0 = (uint32_t)((2 * wid)     * 2048) + (uint32_t)(lane * 16);
    const uint32_t cvtSrc1 = (uint32_t)((2 * wid + 1) * 2048) + (uint32_t)(lane * 16);
    const uint32_t bDst0 = (uint32_t)((2 * wid)     * 1024) + (uint32_t)(lane * 8);
    const uint32_t bDst1 = (uint32_t)((2 * wid + 1) * 1024) + (uint32_t)(lane * 8);

    // ---- A fragment addresses (K-major, swizzled) ----
    uint32_t aOff[4], aXor[4];
#pragma unroll
    for (int mi = 0; mi < 4; ++mi) {
        int r = wm * 64 + mi * 16 + (lane & 15);
        aOff[mi] = (uint32_t)r * 128u;
        aXor[mi] = (uint32_t)(r & 7) << 4;
    }
    const uint32_t aKadd = (uint32_t)(lane >> 4) << 4;

    // ---- B fragment addresses (per-label 1KB MN-major blobs, trans ldsm) ----
    uint32_t bOff[2];
#pragma unroll
    for (int i = 0; i < 2; ++i)
        bOff[i] = (uint32_t)((wn * 4 + 2 * i + (lane >> 4)) * 1024 + (lane & 15) * 16);

    float acc[4][4][4];
#pragma unroll
    for (int mi = 0; mi < 4; ++mi)
#pragma unroll
        for (int ni = 0; ni < 4; ++ni)
#pragma unroll
            for (int k = 0; k < 4; ++k) acc[mi][ni][k] = 0.0f;

    float4 bv[4];   // conversion scratch for ONE label (reused per half)

    auto stageA = [&](int c) {
        const uint32_t ad = sb + (uint32_t)(OFF_A + (c % NSTAGE_A) * A_STAGE) + aDstBase;
        const char* as = aSrc + c * 128;
#pragma unroll
        for (int j = 0; j < 4; ++j) {
            uint32_t u = (uint32_t)(ahalf * 4 + j);
            cpasync16(ad + ((u ^ arx) << 4), as + j * 16);
        }
    };

    auto ldB32 = [&](int c) {      // raw fp32 chunk -> B32 smem (async)
        const char* src = b32Src + (size_t)c * 2048;
        const uint32_t dst = sb + (uint32_t)OFF_B32 + b32Dst;
#pragma unroll
        for (int j = 0; j < 8; ++j)
            cpasync16(dst + j * 256, src + bu0 * 16 + j * 256);
    };

    // convert half h of chunk c: B32(smem fp32) -> bv -> B16[(c)&1]
    auto convB = [&](int c, int h) {
        const uint32_t s = sb + (uint32_t)OFF_B32 + (h == 0 ? cvtSrc0 : cvtSrc1);
#pragma unroll
        for (int j = 0; j < 4; ++j)
            asm volatile("ld.shared.v4.b32 {%0,%1,%2,%3}, [%4];"
                         : "=f"(bv[j].x), "=f"(bv[j].y), "=f"(bv[j].z), "=f"(bv[j].w)
                         : "r"(s + (uint32_t)(j * 512)));
        char* bd = smc + OFF_B16 + (c & 1) * B16_BUF + (h == 0 ? bDst0 : bDst1);
#pragma unroll
        for (int j = 0; j < 4; ++j) {
            uint2 w = make_uint2(pkh2(bv[j].x, bv[j].y), pkh2(bv[j].z, bv[j].w));
            *reinterpret_cast<uint2*>(bd + j * 256) = w;
        }
    };

    // prologue-only: chunk 0 B via direct LDG (B32 not yet filled)
    auto ldgB0 = [&](int h) {
        const float* src = W1 + (size_t)(l0 + 2 * wid + h) * (H * 8);
#pragma unroll
        for (int j = 0; j < 4; ++j)
            bv[j] = *reinterpret_cast<const float4*>(src + j * 128 + lane * 4);
        char* bd = smc + OFF_B16 + (h == 0 ? bDst0 : bDst1);
#pragma unroll
        for (int j = 0; j < 4; ++j) {
            uint2 w = make_uint2(pkh2(bv[j].x, bv[j].y), pkh2(bv[j].z, bv[j].w));
            *reinterpret_cast<uint2*>(bd + j * 256) = w;
        }
    };

    auto compute = [&](int c) {
        const uint32_t bA = sb + (uint32_t)(OFF_A + (c % NSTAGE_A) * A_STAGE);
        const uint32_t bB = sb + (uint32_t)(OFF_B16 + (c & 1) * B16_BUF);
#pragma unroll
        for (int ks = 0; ks < 4; ++ks) {
            const uint32_t koff = (uint32_t)ks * 32u;
            uint32_t a[4][4], b[2][4];
#pragma unroll
            for (int mi = 0; mi < 4; ++mi)
                ldsm4(a[mi], bA + aOff[mi] + ((koff + aKadd) ^ aXor[mi]));
#pragma unroll
            for (int i = 0; i < 2; ++i)
                ldsm4t(b[i], bB + bOff[i] + (uint32_t)ks * 256u);
#pragma unroll
            for (int mi = 0; mi < 4; ++mi)
#pragma unroll
                for (int i = 0; i < 2; ++i) {
                    mma16816(acc[mi][2 * i],     a[mi], &b[i][0]);
                    mma16816(acc[mi][2 * i + 1], a[mi], &b[i][2]);
                }
        }
    };

    // ---- prologue ----
    stageA(0); stageA(1); ldB32(1);
    CP_COMMIT();                 // one group: A(0), A(1), B32(1)
    ldgB0(0); ldgB0(1);          // chunk 0 B16 via direct LDG
    CP_WAIT0();                  // A(0), A(1), B32(1) landed
    __syncthreads();

    // ---- main loop ----
    // invariant at top of chunk c: A(c) ready, B16[c&1] ready, B32 holds chunk c+1 (landed)
    for (int c = 0; c < NCHUNK; ++c) {
        const bool more1 = (c + 1 < NCHUNK);
        const bool more2 = (c + 2 < NCHUNK);

        if (more1) { convB(c + 1, 0); convB(c + 1, 1); }  // LDS B32 -> cvt -> B16[(c+1)&1]
        __syncthreads();             // all B32 reads complete before refill below
        if (more2) {
            ldB32(c + 2); CP_COMMIT();      // group P_c: B32(c+2) — must land by end of c
            stageA(c + 2); CP_COMMIT();     // group Q_c: A(c+2) — consumed at c+2
        }

        compute(c);

        if (more1) {
            // ≤1 pending: P_c drained (B32(c+2) ready for convB at top of c+1);
            // Q_c may remain in flight; Q_{c-1} (A(c+1)) is older → drained.
            if (more2) { CP_WAIT1(); } else { CP_WAIT0(); }
        }
        __syncthreads();
    }

    // ---- epilogue: relu(h + b1) . W2 + b2, quad-reduce, coalesced store ----
    float* eTile = reinterpret_cast<float*>(smc);   // reuse A region (10240 B)
    const int gid = lane >> 2;
    const int tq  = lane & 3;
#pragma unroll
    for (int ni = 0; ni < 4; ++ni) {
        const int l = l0 + wn * 4 + ni;
        float2 bbv = *reinterpret_cast<const float2*>(b1 + (size_t)l * 8 + tq * 2);
        float2 wwv = *reinterpret_cast<const float2*>(W2 + (size_t)l * 8 + tq * 2);
        const float b2v = __ldg(b2 + l);
#pragma unroll
        for (int mi = 0; mi < 4; ++mi) {
            float s0 = fmaxf(acc[mi][ni][0] + bbv.x, 0.0f) * wwv.x
                     + fmaxf(acc[mi][ni][1] + bbv.y, 0.0f) * wwv.y;
            float s1 = fmaxf(acc[mi][ni][2] + bbv.x, 0.0f) * wwv.x
                     + fmaxf(acc[mi][ni][3] + bbv.y, 0.0f) * wwv.y;
            s0 += __shfl_xor_sync(0xffffffffu, s0, 1);
            s0 += __shfl_xor_sync(0xffffffffu, s0, 2);
            s1 += __shfl_xor_sync(0xffffffffu, s1, 1);
            s1 += __shfl_xor_sync(0xffffffffu, s1, 2);
            if (tq == 0) {
                const int r = wm * 64 + mi * 16 + gid;   // local row in [0,128)
                const int cc = wn * 4 + ni;              // local col in [0,16)
                eTile[r * 20 + cc]       = s0 + b2v;
                eTile[(r + 8) * 20 + cc] = s1 + b2v;
            }
        }
    }
    __syncthreads();

#pragma unroll
    for (int i = tid; i < 512; i += 256) {
        const int r = i >> 2;
        const int q = i & 3;
        float4 v = *reinterpret_cast<const float4*>(&eTile[r * 20 + q * 4]);
        *reinterpret_cast<float4*>(out + (size_t)(m0 + r) * L + l0 + q * 4) = v;
    }
}

extern "C" void kernel_launch(void* const* d_in, const int* in_sizes, int n_in,
                              void* d_out, int out_size)
{
    const float* emb = (const float*)d_in[0];  // [B, H]
    const float* W1  = (const float*)d_in[1];  // [L, H, 8]
    const float* b1  = (const float*)d_in[2];  // [L, 8]
    const float* W2  = (const float*)d_in[3];  // [L, 8]
    const float* b2  = (const float*)d_in[4];  // [L]
    float* out       = (float*)d_out;          // [B, L]

    cudaFuncSetAttribute(imec_hmma_kernel,
                         cudaFuncAttributeMaxDynamicSharedMemorySize, SMEM_DYN);

    cvt_emb_kernel<<<BB * H / 4 / 256, 256>>>(emb);
    imec_hmma_kernel<<<(L / LPB) * 2, 256, SMEM_DYN>>>(W1, b1, W2, b2, out);
}